// round 3
// baseline (speedup 1.0000x reference)
#include <cuda_runtime.h>

// sLSTM: B=256, T=512, D=8, H=120, L=4, NH=8, HD=15
// Warp k owns head pair (k, k+4) for two batches as packed f32x2 lanes.
// Input projection (x@W^T + b) hoisted out of the serial scan: precomputed
// 8 steps at a time into registers (parallel, latency-hidden). The scan does
// only the recurrent matvec (15 FMA2 x 4 gates) + cell with a single-exp
// stabilizer. h exchange via shfl (warp-private recurrence, no barriers).
// Down-projection every 64 steps from shared hs history. 128 CTAs x 128 thr.

#define B_ 256
#define T_ 512
#define D_ 8
#define H_ 120
#define L_ 4
#define NPAIR 60
#define ST 61    // hs row stride in ull (odd => low bank conflicts)
#define SUB 8    // precompute granularity (steps)

typedef unsigned long long ull;

__device__ float g_last[B_ * D_];

__device__ __forceinline__ ull f2pack(float x, float y) {
    ull r; asm("mov.b64 %0, {%1, %2};" : "=l"(r) : "f"(x), "f"(y)); return r;
}
__device__ __forceinline__ void f2unpack(ull v, float& x, float& y) {
    asm("mov.b64 {%0, %1}, %2;" : "=f"(x), "=f"(y) : "l"(v));
}
__device__ __forceinline__ float f2lo(ull v) {
    float x, y; f2unpack(v, x, y); return x;
}
__device__ __forceinline__ ull f2fma(ull a, ull b, ull c) {
    ull d; asm("fma.rn.f32x2 %0, %1, %2, %3;" : "=l"(d) : "l"(a), "l"(b), "l"(c));
    return d;
}
__device__ __forceinline__ float tanh_ap(float x) {
    float r; asm("tanh.approx.f32 %0, %1;" : "=f"(r) : "f"(x)); return r;
}
__device__ __forceinline__ float rcp_ap(float x) {
    float r; asm("rcp.approx.f32 %0, %1;" : "=f"(r) : "f"(x)); return r;
}

// sLSTM cell, single-exp stabilizer:
// mn = max(it, ft+m); exactly one of exp(it-mn), exp(ft+m-mn) is 1,
// the other is exp(-|it-(ft+m)|).
__device__ __forceinline__ float cellf(float it, float ft, float zt, float ot,
                                       float& c, float& nn, float& m) {
    float b = ft + m;
    float mn = fmaxf(it, b);
    float e = __expf(-fabsf(it - b));
    bool ag = (it >= b);
    float ip = ag ? 1.f : e;
    float fp = ag ? e : 1.f;
    float z  = tanh_ap(zt);
    c  = fp * c  + ip * z;
    nn = fp * nn + ip;
    m  = mn;
    float o = fmaf(tanh_ap(0.5f * ot), 0.5f, 0.5f);   // sigmoid
    return o * c * rcp_ap(nn);
}

// shared layout (ull units):
//   x2   [2][512*8]   = 8192   residual/x stream, duplicated (v,v)
//   hsb  [2][64*ST]   = 7808   64-step h history (paired)
//   win2 [4][60*8]    = 1920   paired input weights (gate-major)
//   wp2  [8*60]       = 480    paired Wp
//   bps  [8 floats]   = 4
#define SM_X2  0
#define SM_HS  8192
#define SM_WIN (8192 + 7808)
#define SM_WP  (SM_WIN + 1920)
#define SM_BP  (SM_WP + 480)
#define SM_TOT (SM_BP + 4)
#define SMEM_BYTES (SM_TOT * 8 + 16)

__global__ void __launch_bounds__(128, 1) slstm_kernel(
    const float* __restrict__ X,
    const float* __restrict__ Wi, const float* __restrict__ Wf,
    const float* __restrict__ Wz, const float* __restrict__ Wo,
    const float* __restrict__ Ri, const float* __restrict__ Rf,
    const float* __restrict__ Rz, const float* __restrict__ Ro,
    const float* __restrict__ bi, const float* __restrict__ bf,
    const float* __restrict__ bz, const float* __restrict__ bo,
    const float* __restrict__ Wp, const float* __restrict__ bp)
{
    extern __shared__ ull sm[];
    ull* x2   = sm + SM_X2;
    ull* hsb  = sm + SM_HS;
    ull* win2 = sm + SM_WIN;
    ull* wp2  = sm + SM_WP;
    float* bps = (float*)(sm + SM_BP);

    const int tid  = threadIdx.x;
    const int lane = tid & 31;
    const int k    = tid >> 5;           // warp id == head block (pairs k+4)
    const int half = (lane >> 4) & 1;    // batch within CTA
    const int e    = lane & 15;
    const bool act = (e < 15);
    const int b0   = blockIdx.x * 2;
    const int srcbase = lane & 16;
    const int slot = k * 15 + (act ? e : 0);   // clamped pair slot

    // load input x for both batches, duplicated (v,v)
    for (int idx = tid; idx < 2 * T_ * D_; idx += 128) {
        int bbi = idx >> 12;
        int i   = idx & 4095;
        float v = X[(b0 + bbi) * (T_ * D_) + i];
        x2[bbi * 4096 + i] = f2pack(v, v);
    }

    #pragma unroll 1
    for (int l = 0; l < L_; l++) {
        // ---- recurrent weights (packed) into registers ----
        ull rIv[15], rFv[15], rZv[15], rOv[15];
        ull bIv, bFv, bZv, bOv;
        {
            const float* ri = Ri + l * 8 * 225;
            const float* rf = Rf + l * 8 * 225;
            const float* rz = Rz + l * 8 * 225;
            const float* ro = Ro + l * 8 * 225;
            #pragma unroll
            for (int d = 0; d < 15; d++) {
                int ee = act ? e : 0;
                int i0 = k * 225 + d * 15 + ee;
                int i1 = (k + 4) * 225 + d * 15 + ee;
                rIv[d] = act ? f2pack(ri[i0], ri[i1]) : 0ull;
                rFv[d] = act ? f2pack(rf[i0], rf[i1]) : 0ull;
                rZv[d] = act ? f2pack(rz[i0], rz[i1]) : 0ull;
                rOv[d] = act ? f2pack(ro[i0], ro[i1]) : 0ull;
            }
            bIv = f2pack(bi[l * H_ + slot], bi[l * H_ + slot + 60]);
            bFv = f2pack(bf[l * H_ + slot], bf[l * H_ + slot + 60]);
            bZv = f2pack(bz[l * H_ + slot], bz[l * H_ + slot + 60]);
            bOv = f2pack(bo[l * H_ + slot], bo[l * H_ + slot + 60]);
        }
        // ---- paired input weights (gate-major), Wp, bp into shared ----
        for (int idx = tid; idx < 4 * NPAIR * 8; idx += 128) {
            int g = idx / 480, r = idx - g * 480;
            int s = r >> 3, d = r & 7;
            const float* w = (g == 0) ? Wi : (g == 1) ? Wf : (g == 2) ? Wz : Wo;
            w += l * H_ * D_;
            win2[idx] = f2pack(w[s * 8 + d], w[(s + 60) * 8 + d]);
        }
        for (int idx = tid; idx < 8 * NPAIR; idx += 128) {
            int d = idx / NPAIR, p = idx - d * NPAIR;
            const float* wp = Wp + l * D_ * H_;
            wp2[idx] = f2pack(wp[d * H_ + p], wp[d * H_ + p + 60]);
        }
        if (tid < 8) bps[tid] = bp[l * D_ + tid];
        __syncthreads();

        float c0 = 0.f, c1 = 0.f, n0 = 0.f, n1 = 0.f, m0 = 0.f, m1 = 0.f;
        float h0 = 0.f, h1 = 0.f;

        #pragma unroll 1
        for (int ch = 0; ch < 8; ch++) {
            const int tbase = ch * 64;
            #pragma unroll 1
            for (int ss = 0; ss < 64 / SUB; ss++) {
                const int t0 = tbase + ss * SUB;
                // ---- precompute gate pre-activations for SUB steps ----
                ull gI[SUB], gF[SUB], gZ[SUB], gO[SUB];
                #pragma unroll
                for (int q = 0; q < SUB; q++) {
                    gI[q] = bIv; gF[q] = bFv; gZ[q] = bZv; gO[q] = bOv;
                }
                {
                    const ull* __restrict__ xr = x2 + half * 4096 + t0 * 8;
                    #pragma unroll
                    for (int d = 0; d < 8; d++) {
                        ull wi_ = win2[0 * 480 + slot * 8 + d];
                        ull wf_ = win2[1 * 480 + slot * 8 + d];
                        ull wz_ = win2[2 * 480 + slot * 8 + d];
                        ull wo_ = win2[3 * 480 + slot * 8 + d];
                        #pragma unroll
                        for (int q = 0; q < SUB; q++) {
                            ull xv = xr[q * 8 + d];
                            gI[q] = f2fma(xv, wi_, gI[q]);
                            gF[q] = f2fma(xv, wf_, gF[q]);
                            gZ[q] = f2fma(xv, wz_, gZ[q]);
                            gO[q] = f2fma(xv, wo_, gO[q]);
                        }
                    }
                }
                // ---- serial scan over SUB steps (warp-private, shfl h) ----
                #pragma unroll
                for (int q = 0; q < SUB; q++) {
                    ull aI = gI[q], aF = gF[q], aZ = gZ[q], aO = gO[q];
                    #pragma unroll
                    for (int d = 0; d < 15; d++) {
                        float hv0 = __shfl_sync(0xffffffffu, h0, srcbase + d);
                        float hv1 = __shfl_sync(0xffffffffu, h1, srcbase + d);
                        ull hv = f2pack(hv0, hv1);
                        aI = f2fma(hv, rIv[d], aI);
                        aF = f2fma(hv, rFv[d], aF);
                        aZ = f2fma(hv, rZv[d], aZ);
                        aO = f2fma(hv, rOv[d], aO);
                    }
                    float itx, ity, ftx, fty, ztx, zty, otx, oty;
                    f2unpack(aI, itx, ity); f2unpack(aF, ftx, fty);
                    f2unpack(aZ, ztx, zty); f2unpack(aO, otx, oty);
                    h0 = cellf(itx, ftx, ztx, otx, c0, n0, m0);
                    h1 = cellf(ity, fty, zty, oty, c1, n1, m1);
                    if (act)
                        hsb[half * (64 * ST) + (ss * SUB + q) * ST + slot]
                            = f2pack(h0, h1);
                }
            }
            __syncthreads();
            // ---- projection: x[t] += hs[t] @ Wp^T + bp (64-step chunk) ----
            {
                const int tl = tid & 63;
                const int bb = tid >> 6;
                ull acc[8];
                #pragma unroll
                for (int d = 0; d < 8; d++) acc[d] = 0ull;
                const ull* __restrict__ hsr = hsb + bb * (64 * ST) + tl * ST;
                #pragma unroll 4
                for (int p = 0; p < NPAIR; p++) {
                    ull hv = hsr[p];
                    #pragma unroll
                    for (int d = 0; d < 8; d++)
                        acc[d] = f2fma(hv, wp2[d * NPAIR + p], acc[d]);
                }
                ull* xw = x2 + bb * 4096 + (tbase + tl) * 8;
                #pragma unroll
                for (int d = 0; d < 8; d++) {
                    float ax, ay; f2unpack(acc[d], ax, ay);
                    float nv = f2lo(xw[d]) + ax + ay + bps[d];
                    xw[d] = f2pack(nv, nv);
                }
            }
            __syncthreads();
        }
    }

    if (tid < 16) {
        int bbi = tid >> 3, d = tid & 7;
        g_last[(b0 + bbi) * D_ + d] = f2lo(x2[bbi * 4096 + 511 * 8 + d]);
    }
}

__global__ void finalize_kernel(const float* __restrict__ gamma,
                                const float* __restrict__ beta,
                                const float* __restrict__ wfc,
                                const float* __restrict__ bfc,
                                float* __restrict__ out)
{
    __shared__ float red[8][8];
    __shared__ float smu[8], svar[8];
    int b = threadIdx.x;
    int lane = b & 31, w = b >> 5;
    float v[8];
    #pragma unroll
    for (int d = 0; d < 8; d++) v[d] = g_last[b * 8 + d];

    #pragma unroll
    for (int d = 0; d < 8; d++) {
        float sv = v[d];
        #pragma unroll
        for (int o = 16; o > 0; o >>= 1) sv += __shfl_xor_sync(0xffffffffu, sv, o);
        if (lane == 0) red[d][w] = sv;
    }
    __syncthreads();
    if (b < 8) {
        float sv = 0.f;
        #pragma unroll
        for (int kk = 0; kk < 8; kk++) sv += red[b][kk];
        smu[b] = sv * (1.f / 256.f);
    }
    __syncthreads();
    float mu[8];
    #pragma unroll
    for (int d = 0; d < 8; d++) mu[d] = smu[d];
    __syncthreads();

    #pragma unroll
    for (int d = 0; d < 8; d++) {
        float dv = v[d] - mu[d];
        float sv = dv * dv;
        #pragma unroll
        for (int o = 16; o > 0; o >>= 1) sv += __shfl_xor_sync(0xffffffffu, sv, o);
        if (lane == 0) red[d][w] = sv;
    }
    __syncthreads();
    if (b < 8) {
        float sv = 0.f;
        #pragma unroll
        for (int kk = 0; kk < 8; kk++) sv += red[b][kk];
        svar[b] = sv * (1.f / 256.f);
    }
    __syncthreads();

    float acc = bfc[0];
    #pragma unroll
    for (int d = 0; d < 8; d++) {
        float bn = (v[d] - mu[d]) * rsqrtf(svar[d] + 1e-5f) * gamma[d] + beta[d];
        acc = fmaf(bn, wfc[d], acc);
    }
    out[b] = 1.f / (1.f + expf(-acc));
}

extern "C" void kernel_launch(void* const* d_in, const int* in_sizes, int n_in,
                              void* d_out, int out_size) {
    const float* X    = (const float*)d_in[0];
    const float* Wi   = (const float*)d_in[1];
    const float* Wf   = (const float*)d_in[2];
    const float* Wz   = (const float*)d_in[3];
    const float* Wo   = (const float*)d_in[4];
    const float* Ri   = (const float*)d_in[5];
    const float* Rf   = (const float*)d_in[6];
    const float* Rz   = (const float*)d_in[7];
    const float* Ro   = (const float*)d_in[8];
    const float* bi   = (const float*)d_in[9];
    const float* bf   = (const float*)d_in[10];
    const float* bz   = (const float*)d_in[11];
    const float* bo   = (const float*)d_in[12];
    const float* Wp   = (const float*)d_in[13];
    const float* bp   = (const float*)d_in[14];
    const float* gam  = (const float*)d_in[15];
    const float* bet  = (const float*)d_in[16];
    const float* Wfc  = (const float*)d_in[17];
    const float* bfc  = (const float*)d_in[18];

    cudaFuncSetAttribute(slstm_kernel,
                         cudaFuncAttributeMaxDynamicSharedMemorySize, SMEM_BYTES);
    slstm_kernel<<<128, 128, SMEM_BYTES>>>(X, Wi, Wf, Wz, Wo, Ri, Rf, Rz, Ro,
                                           bi, bf, bz, bo, Wp, bp);
    finalize_kernel<<<1, 256>>>(gam, bet, Wfc, bfc, (float*)d_out);
}

// round 4
// speedup vs baseline: 1.5523x; 1.5523x over previous
#include <cuda_runtime.h>

// sLSTM: B=256, T=512, D=8, H=120, L=4, NH=8, HD=15
// R2 structure (winner so far) with the per-step SHFLs removed:
//  - warp k owns head pair (k,k+4) for 2 batches (lanes 0-14 / 16-30), each
//    lane computing packed f32x2 output pair (j, j+60) via FFMA2.
//  - h exchange through the hs history buffer as a warp-private ring:
//    write h[tt], read h[tt-1] as 15 broadcast LDS.64. No SHFL, no pack.
//  - scan loop unrolled x2 so next step's input FMAs hide the cell tail.
//  - down-projection every 64 steps, residual written back into x stream.
// 128 CTAs x 128 threads (1 CTA/SM, 1 warp/SMSP).

#define B_ 256
#define T_ 512
#define D_ 8
#define H_ 120
#define L_ 4
#define NPAIR 60
#define ST 61              // hs row stride (ull)
#define BST (64 * ST + 1)  // hs batch stride (ull), +1 to split banks
#define XST 4097           // x batch stride (ull), +1 to split banks

typedef unsigned long long ull;

__device__ float g_last[B_ * D_];

__device__ __forceinline__ ull f2pack(float x, float y) {
    ull r; asm("mov.b64 %0, {%1, %2};" : "=l"(r) : "f"(x), "f"(y)); return r;
}
__device__ __forceinline__ void f2unpack(ull v, float& x, float& y) {
    asm("mov.b64 {%0, %1}, %2;" : "=f"(x), "=f"(y) : "l"(v));
}
__device__ __forceinline__ float f2lo(ull v) {
    float x, y; f2unpack(v, x, y); return x;
}
__device__ __forceinline__ ull f2fma(ull a, ull b, ull c) {
    ull d; asm("fma.rn.f32x2 %0, %1, %2, %3;" : "=l"(d) : "l"(a), "l"(b), "l"(c));
    return d;
}
__device__ __forceinline__ float tanh_ap(float x) {
    float r; asm("tanh.approx.f32 %0, %1;" : "=f"(r) : "f"(x)); return r;
}
__device__ __forceinline__ float rcp_ap(float x) {
    float r; asm("rcp.approx.f32 %0, %1;" : "=f"(r) : "f"(x)); return r;
}

// sLSTM cell, single-exp stabilizer:
// mn = max(it, ft+m); one of the exps is exactly 1, other = exp(-|it-(ft+m)|).
__device__ __forceinline__ float cellf(float it, float ft, float zt, float ot,
                                       float& c, float& nn, float& m) {
    float z  = tanh_ap(zt);                           // start MUFUs early
    float o  = fmaf(tanh_ap(0.5f * ot), 0.5f, 0.5f);  // sigmoid via tanh
    float b  = ft + m;
    float mn = fmaxf(it, b);
    float e  = __expf(-fabsf(it - b));
    bool ag  = (it >= b);
    float ip = ag ? 1.f : e;
    float fp = ag ? e : 1.f;
    c  = fp * c  + ip * z;
    nn = fp * nn + ip;
    m  = mn;
    return o * c * rcp_ap(nn);
}

// shared layout (ull units):
//   x2  [2][XST]  = 8194   residual/x stream, duplicated (v,v)
//   hsb [2][BST]  = 7810   h history ring (paired), rows of ST
//   wp2 [8*60]    = 480
//   bps [8 floats]
#define SM_X2  0
#define SM_HS  (2 * XST)
#define SM_WP  (SM_HS + 2 * BST)
#define SM_BP  (SM_WP + 480)
#define SM_TOT (SM_BP + 4)
#define SMEM_BYTES (SM_TOT * 8 + 16)

__global__ void __launch_bounds__(128, 1) slstm_kernel(
    const float* __restrict__ X,
    const float* __restrict__ Wi, const float* __restrict__ Wf,
    const float* __restrict__ Wz, const float* __restrict__ Wo,
    const float* __restrict__ Ri, const float* __restrict__ Rf,
    const float* __restrict__ Rz, const float* __restrict__ Ro,
    const float* __restrict__ bi, const float* __restrict__ bf,
    const float* __restrict__ bz, const float* __restrict__ bo,
    const float* __restrict__ Wp, const float* __restrict__ bp)
{
    extern __shared__ ull sm[];
    ull* x2  = sm + SM_X2;
    ull* hsb = sm + SM_HS;
    ull* wp2 = sm + SM_WP;
    float* bps = (float*)(sm + SM_BP);

    const int tid  = threadIdx.x;
    const int lane = tid & 31;
    const int k    = tid >> 5;           // warp id == head block (pairs k+4)
    const int half = (lane >> 4) & 1;    // batch within CTA
    const int e    = lane & 15;
    const bool act = (e < 15);
    const int b0   = blockIdx.x * 2;
    const int slot = k * 15 + (act ? e : 14);

    // load input x for both batches, duplicated (v,v)
    for (int idx = tid; idx < 2 * T_ * D_; idx += 128) {
        int bbi = idx >> 12;
        int i   = idx & 4095;
        float v = X[(b0 + bbi) * (T_ * D_) + i];
        x2[bbi * XST + i] = f2pack(v, v);
    }

    #pragma unroll 1
    for (int l = 0; l < L_; l++) {
        // ---- packed weights into registers ----
        ull rIv[15], rFv[15], rZv[15], rOv[15];
        ull wIv[8],  wFv[8],  wZv[8],  wOv[8];
        ull bIv, bFv, bZv, bOv;
        {
            const int j0 = slot, j1 = slot + 60;
            const float* wi = Wi + l * H_ * D_;
            const float* wf = Wf + l * H_ * D_;
            const float* wz = Wz + l * H_ * D_;
            const float* wo = Wo + l * H_ * D_;
            #pragma unroll
            for (int d = 0; d < 8; d++) {
                wIv[d] = f2pack(wi[j0 * 8 + d], wi[j1 * 8 + d]);
                wFv[d] = f2pack(wf[j0 * 8 + d], wf[j1 * 8 + d]);
                wZv[d] = f2pack(wz[j0 * 8 + d], wz[j1 * 8 + d]);
                wOv[d] = f2pack(wo[j0 * 8 + d], wo[j1 * 8 + d]);
            }
            const float* ri = Ri + l * 8 * 225;
            const float* rf = Rf + l * 8 * 225;
            const float* rz = Rz + l * 8 * 225;
            const float* ro = Ro + l * 8 * 225;
            const int ee = act ? e : 14;
            #pragma unroll
            for (int d = 0; d < 15; d++) {
                int i0 = k * 225 + d * 15 + ee;
                int i1 = (k + 4) * 225 + d * 15 + ee;
                rIv[d] = f2pack(ri[i0], ri[i1]);
                rFv[d] = f2pack(rf[i0], rf[i1]);
                rZv[d] = f2pack(rz[i0], rz[i1]);
                rOv[d] = f2pack(ro[i0], ro[i1]);
            }
            bIv = f2pack(bi[l * H_ + j0], bi[l * H_ + j1]);
            bFv = f2pack(bf[l * H_ + j0], bf[l * H_ + j1]);
            bZv = f2pack(bz[l * H_ + j0], bz[l * H_ + j1]);
            bOv = f2pack(bo[l * H_ + j0], bo[l * H_ + j1]);
        }
        for (int idx = tid; idx < 8 * NPAIR; idx += 128) {
            int d = idx / NPAIR, p = idx - d * NPAIR;
            const float* wp = Wp + l * D_ * H_;
            wp2[idx] = f2pack(wp[d * H_ + p], wp[d * H_ + p + 60]);
        }
        if (tid < 8) bps[tid] = bp[l * D_ + tid];
        // zero the ring's "step -1" row (read by tt=0 of chunk 0)
        if (act) {
            hsb[0 * BST + 63 * ST + slot] = 0ull;
            hsb[1 * BST + 63 * ST + slot] = 0ull;
        }
        __syncthreads();

        float c0 = 0.f, c1 = 0.f, n0 = 0.f, n1 = 0.f, m0 = 0.f, m1 = 0.f;

        ull* __restrict__ hrow = hsb + half * BST;   // this half's ring
        const int hoff = k * 15;

        #pragma unroll 1
        for (int ch = 0; ch < 8; ch++) {
            const int tbase = ch * 64;
            // ---- scan 64 steps: warp-private ring, no CTA barriers ----
            #pragma unroll 2
            for (int tt = 0; tt < 64; tt++) {
                const int p = (tt - 1) & 63;
                ull aI = bIv, aF = bFv, aZ = bZv, aO = bOv;
                const ull* __restrict__ xr = x2 + half * XST + (tbase + tt) * 8;
                #pragma unroll
                for (int d = 0; d < 8; d++) {
                    ull xv = xr[d];
                    aI = f2fma(xv, wIv[d], aI);
                    aF = f2fma(xv, wFv[d], aF);
                    aZ = f2fma(xv, wZv[d], aZ);
                    aO = f2fma(xv, wOv[d], aO);
                }
                const ull* __restrict__ hr = hrow + p * ST + hoff;
                #pragma unroll
                for (int d = 0; d < 15; d++) {
                    ull hv = hr[d];
                    aI = f2fma(hv, rIv[d], aI);
                    aF = f2fma(hv, rFv[d], aF);
                    aZ = f2fma(hv, rZv[d], aZ);
                    aO = f2fma(hv, rOv[d], aO);
                }
                float itx, ity, ftx, fty, ztx, zty, otx, oty;
                f2unpack(aI, itx, ity); f2unpack(aF, ftx, fty);
                f2unpack(aZ, ztx, zty); f2unpack(aO, otx, oty);
                float h0 = cellf(itx, ftx, ztx, otx, c0, n0, m0);
                float h1 = cellf(ity, fty, zty, oty, c1, n1, m1);
                if (act)
                    hrow[tt * ST + slot] = f2pack(h0, h1);
                __syncwarp();
            }
            __syncthreads();
            // ---- projection: x[t] += hs[t] @ Wp^T + bp (64-step chunk) ----
            {
                const int tl = tid & 63;
                const int bb = tid >> 6;
                ull acc[8];
                #pragma unroll
                for (int d = 0; d < 8; d++) acc[d] = 0ull;
                const ull* __restrict__ hsr = hsb + bb * BST + tl * ST;
                #pragma unroll 4
                for (int p = 0; p < NPAIR; p++) {
                    ull hv = hsr[p];
                    #pragma unroll
                    for (int d = 0; d < 8; d++)
                        acc[d] = f2fma(hv, wp2[d * NPAIR + p], acc[d]);
                }
                ull* xw = x2 + bb * XST + (tbase + tl) * 8;
                #pragma unroll
                for (int d = 0; d < 8; d++) {
                    float ax, ay; f2unpack(acc[d], ax, ay);
                    float nv = f2lo(xw[d]) + ax + ay + bps[d];
                    xw[d] = f2pack(nv, nv);
                }
            }
            __syncthreads();
        }
    }

    if (tid < 16) {
        int bbi = tid >> 3, d = tid & 7;
        g_last[(b0 + bbi) * D_ + d] = f2lo(x2[bbi * XST + 511 * 8 + d]);
    }
}

__global__ void finalize_kernel(const float* __restrict__ gamma,
                                const float* __restrict__ beta,
                                const float* __restrict__ wfc,
                                const float* __restrict__ bfc,
                                float* __restrict__ out)
{
    __shared__ float red[8][8];
    __shared__ float smu[8], svar[8];
    int b = threadIdx.x;
    int lane = b & 31, w = b >> 5;
    float v[8];
    #pragma unroll
    for (int d = 0; d < 8; d++) v[d] = g_last[b * 8 + d];

    #pragma unroll
    for (int d = 0; d < 8; d++) {
        float sv = v[d];
        #pragma unroll
        for (int o = 16; o > 0; o >>= 1) sv += __shfl_xor_sync(0xffffffffu, sv, o);
        if (lane == 0) red[d][w] = sv;
    }
    __syncthreads();
    if (b < 8) {
        float sv = 0.f;
        #pragma unroll
        for (int kk = 0; kk < 8; kk++) sv += red[b][kk];
        smu[b] = sv * (1.f / 256.f);
    }
    __syncthreads();
    float mu[8];
    #pragma unroll
    for (int d = 0; d < 8; d++) mu[d] = smu[d];
    __syncthreads();

    #pragma unroll
    for (int d = 0; d < 8; d++) {
        float dv = v[d] - mu[d];
        float sv = dv * dv;
        #pragma unroll
        for (int o = 16; o > 0; o >>= 1) sv += __shfl_xor_sync(0xffffffffu, sv, o);
        if (lane == 0) red[d][w] = sv;
    }
    __syncthreads();
    if (b < 8) {
        float sv = 0.f;
        #pragma unroll
        for (int kk = 0; kk < 8; kk++) sv += red[b][kk];
        svar[b] = sv * (1.f / 256.f);
    }
    __syncthreads();

    float acc = bfc[0];
    #pragma unroll
    for (int d = 0; d < 8; d++) {
        float bn = (v[d] - mu[d]) * rsqrtf(svar[d] + 1e-5f) * gamma[d] + beta[d];
        acc = fmaf(bn, wfc[d], acc);
    }
    out[b] = 1.f / (1.f + expf(-acc));
}

extern "C" void kernel_launch(void* const* d_in, const int* in_sizes, int n_in,
                              void* d_out, int out_size) {
    const float* X    = (const float*)d_in[0];
    const float* Wi   = (const float*)d_in[1];
    const float* Wf   = (const float*)d_in[2];
    const float* Wz   = (const float*)d_in[3];
    const float* Wo   = (const float*)d_in[4];
    const float* Ri   = (const float*)d_in[5];
    const float* Rf   = (const float*)d_in[6];
    const float* Rz   = (const float*)d_in[7];
    const float* Ro   = (const float*)d_in[8];
    const float* bi   = (const float*)d_in[9];
    const float* bf   = (const float*)d_in[10];
    const float* bz   = (const float*)d_in[11];
    const float* bo   = (const float*)d_in[12];
    const float* Wp   = (const float*)d_in[13];
    const float* bp   = (const float*)d_in[14];
    const float* gam  = (const float*)d_in[15];
    const float* bet  = (const float*)d_in[16];
    const float* Wfc  = (const float*)d_in[17];
    const float* bfc  = (const float*)d_in[18];

    cudaFuncSetAttribute(slstm_kernel,
                         cudaFuncAttributeMaxDynamicSharedMemorySize, SMEM_BYTES);
    slstm_kernel<<<128, 128, SMEM_BYTES>>>(X, Wi, Wf, Wz, Wo, Ri, Rf, Rz, Ro,
                                           bi, bf, bz, bo, Wp, bp);
    finalize_kernel<<<1, 256>>>(gam, bet, Wfc, bfc, (float*)d_out);
}